// round 5
// baseline (speedup 1.0000x reference)
#include <cuda_runtime.h>
#include <stdint.h>

// Problem constants
#define PQ 400
#define PP 200000
#define NB 100
#define NCTA 148
#define NTH 256
#define NWARP_TOT (NCTA * 8)        // 1184 warps chip-wide
#define ROW_F4 (PP / 4)             // 50,000 float4 per row
#define TOT_F4 ((long long)PQ * ROW_F4)  // 20,000,000

typedef unsigned long long u64;
typedef unsigned int u32;

// Device scratch (no allocations allowed)
__device__ unsigned char d_lab8[PP];
__device__ float d_GN[NB * PQ];   // sum of (sel - 0.25(A+B)) = -(f1-f0) per (label,q)
__device__ float d_Pb[NB * PQ];   // sum of sigmoid per (label,q)
__device__ float d_Sel[PQ];       // sum of sel per q
__device__ int   d_cnt[NB];

// ---------------------------------------------------------------------------
// f32x2 helpers (Blackwell packed-FP32; PTX-only path)
// ---------------------------------------------------------------------------
#define FMA2(d, a, b, c) asm("fma.rn.f32x2 %0, %1, %2, %3;" : "=l"(d) : "l"(a), "l"(b), "l"(c))
#define MUL2(d, a, b)    asm("mul.rn.f32x2 %0, %1, %2;"     : "=l"(d) : "l"(a), "l"(b))
#define ADD2(d, a, b)    asm("add.rn.f32x2 %0, %1, %2;"     : "=l"(d) : "l"(a), "l"(b))

__device__ __forceinline__ u64 pk2(float lo, float hi) {
    u64 r; asm("mov.b64 %0, {%1, %2};" : "=l"(r) : "f"(lo), "f"(hi)); return r;
}
__device__ __forceinline__ u64 bcast2(float v) {
    u64 r; asm("mov.b64 %0, {%1, %1};" : "=l"(r) : "f"(v)); return r;
}
__device__ __forceinline__ void upk2(u64 v, float& lo, float& hi) {
    asm("mov.b64 {%0, %1}, %2;" : "=f"(lo), "=f"(hi) : "l"(v));
}
__device__ __forceinline__ float ex2f(float x) {
    float r; asm("ex2.approx.ftz.f32 %0, %1;" : "=f"(r) : "f"(x)); return r;
}
__device__ __forceinline__ float rcpf(float x) {
    float r; asm("rcp.approx.ftz.f32 %0, %1;" : "=f"(r) : "f"(x)); return r;
}
__device__ __forceinline__ float slctf(float a, float b, float c) { // c>=0 ? a : b
    float d; asm("slct.f32.f32 %0, %1, %2, %3;" : "=f"(d) : "f"(a), "f"(b), "f"(c)); return d;
}
__device__ __forceinline__ u32 smem_u32(const void* p) {
    u32 a; asm("{ .reg .u64 t; cvta.to.shared.u64 t, %1; cvt.u32.u64 %0, t; }" : "=r"(a) : "l"(p));
    return a;
}

// Private-column bin RMW: ld.shared.b64 + packed add + st.shared.b64 (no atomics)
__device__ __forceinline__ void bin_rmw(u32 addr, u64 add) {
    u64 v;
    asm volatile("ld.shared.b64 %0, [%1];" : "=l"(v) : "r"(addr));
    ADD2(v, v, add);
    asm volatile("st.shared.b64 [%0], %1;" :: "r"(addr), "l"(v) : "memory");
}

// Loop-invariant packed constants
struct PkConsts {
    u64 nl2e, one, two, neg1;
    u64 c6, c5, c4, c3, c2, c1, c0;
    u64 negq;
};
__device__ __forceinline__ PkConsts make_consts() {
    PkConsts K;
    K.nl2e = bcast2(-1.4426950408889634f);
    K.one  = bcast2(1.0f);
    K.two  = bcast2(2.0f);
    K.neg1 = bcast2(-1.0f);
    // log1p(e) = ln(3/2) + ln(1 + u/3), u = 2e-1, Taylor deg 7
    K.c6 = bcast2(-2.2862368e-4f);
    K.c5 = bcast2( 8.2304527e-4f);
    K.c4 = bcast2(-3.0864198e-3f);
    K.c3 = bcast2( 1.2345679e-2f);
    K.c2 = bcast2(-5.5555556e-2f);
    K.c1 = bcast2( 3.3333333e-1f);
    K.c0 = bcast2( 4.0546511e-1f);
    K.negq = bcast2(-0.25f);
    return K;
}

// ---------------------------------------------------------------------------
// pair2: 2 elements -> per-element packed (gneg, p) for bins; selacc += sel
//   e = exp(-|x|), s = 1/(1+e), L = log1p(e), os = e*s
//   A = os^2 L, B = s^2 (|x|+L)
//   sel = x<0 ? A : B ; p = x<0 ? os : s
//   gneg = sel - 0.25(A+B) = -(f1 - f0)
// ---------------------------------------------------------------------------
__device__ __forceinline__ void pair2(u64 X, const PkConsts& K,
                                      u64& bin0, u64& bin1, u64& selacc) {
    u64 AX = X & 0x7FFFFFFF7FFFFFFFull;
    u64 T;  MUL2(T, AX, K.nl2e);
    float t0, t1; upk2(T, t0, t1);
    u64 E = pk2(ex2f(t0), ex2f(t1));
    u64 EP1; ADD2(EP1, E, K.one);
    float q0, q1; upk2(EP1, q0, q1);
    u64 S = pk2(rcpf(q0), rcpf(q1));

    u64 U; FMA2(U, E, K.two, K.neg1);
    u64 L;
    FMA2(L, U, K.c6, K.c5);
    FMA2(L, L, U, K.c4);
    FMA2(L, L, U, K.c3);
    FMA2(L, L, U, K.c2);
    FMA2(L, L, U, K.c1);
    FMA2(L, L, U, K.c0);

    u64 OS;  MUL2(OS, E, S);
    u64 AXL; ADD2(AXL, AX, L);
    u64 OS2; MUL2(OS2, OS, OS);
    u64 Apk; MUL2(Apk, OS2, L);
    u64 S2;  MUL2(S2, S, S);
    u64 Bpk; MUL2(Bpk, S2, AXL);
    u64 ABpk; ADD2(ABpk, Apk, Bpk);

    float a0, a1, b0, b1, x0, x1, os0, os1, s0, s1;
    upk2(Apk, a0, a1); upk2(Bpk, b0, b1);
    upk2(X, x0, x1); upk2(OS, os0, os1); upk2(S, s0, s1);

    float sel0 = slctf(b0, a0, x0);   // x>=0 ? B : A
    float sel1 = slctf(b1, a1, x1);
    float p0   = slctf(s0, os0, x0);  // x>=0 ? s : os
    float p1   = slctf(s1, os1, x1);

    u64 SEL = pk2(sel0, sel1);
    u64 GN;  FMA2(GN, ABpk, K.negq, SEL);   // gneg = sel - 0.25(A+B)
    ADD2(selacc, selacc, SEL);

    float gn0, gn1; upk2(GN, gn0, gn1);
    bin0 = pk2(gn0, p0);
    bin1 = pk2(gn1, p1);
}

// ---------------------------------------------------------------------------
// Main kernel: flat warp-range distribution, per-thread bin columns, no atomics
// ---------------------------------------------------------------------------
__global__ __launch_bounds__(NTH, 1) void cost_kernel(const float* __restrict__ pm) {
    extern __shared__ u64 bins[];   // [NB][NTH], column = tid (thread-private)
    int tid = threadIdx.x, wid = tid >> 5, lane = tid & 31;

    // Zero own column — private, no sync needed
    #pragma unroll 4
    for (int j = 0; j < NB; j++) bins[j * NTH + tid] = 0ull;

    const PkConsts K = make_consts();
    u32 sb = smem_u32(bins) + (u32)tid * 8u;

    u64 gw = (u64)blockIdx.x * 8 + (u64)wid;
    long long beg = (long long)(gw * (u64)TOT_F4 / NWARP_TOT);
    long long end = (long long)((gw + 1) * (u64)TOT_F4 / NWARP_TOT);

    const uchar4* lv = reinterpret_cast<const uchar4*>(d_lab8);

    while (beg < end) {
        int row = (int)(beg / ROW_F4);
        long long rend = (long long)(row + 1) * ROW_F4;
        if (rend > end) rend = end;
        int c0 = (int)(beg - (long long)row * ROW_F4);
        int cn = (int)(rend - (long long)row * ROW_F4);

        const float4* xr = reinterpret_cast<const float4*>(pm + (size_t)row * PP);

        u64 selpk = 0ull;
        #pragma unroll 2
        for (int c = c0 + lane; c < cn; c += 32) {
            float4 x = __ldcs(xr + c);      // streaming, coalesced 512B/warp
            uchar4 lb = lv[c];              // L2-hot, coalesced 128B/warp
            u64 b0, b1, b2, b3;
            pair2(pk2(x.x, x.y), K, b0, b1, selpk);
            pair2(pk2(x.z, x.w), K, b2, b3, selpk);
            bin_rmw(sb + (u32)lb.x * (NTH * 8u), b0);
            bin_rmw(sb + (u32)lb.y * (NTH * 8u), b1);
            bin_rmw(sb + (u32)lb.z * (NTH * 8u), b2);
            bin_rmw(sb + (u32)lb.w * (NTH * 8u), b3);
        }

        // ---- segment flush (warp-uniform: same row for all lanes) ----
        {
            float slo, shi; upk2(selpk, slo, shi);
            float sv = slo + shi;
            #pragma unroll
            for (int o = 16; o; o >>= 1)
                sv += __shfl_xor_sync(0xFFFFFFFFu, sv, o);
            if (lane == 0) atomicAdd(&d_Sel[row], sv);

            for (int j = 0; j < NB; j++) {
                u64 v = bins[j * NTH + tid];
                bins[j * NTH + tid] = 0ull;
                float lo, hi; upk2(v, lo, hi);
                #pragma unroll
                for (int o = 16; o; o >>= 1) {
                    lo += __shfl_xor_sync(0xFFFFFFFFu, lo, o);
                    hi += __shfl_xor_sync(0xFFFFFFFFu, hi, o);
                }
                if (lane == 0) {
                    atomicAdd(&d_GN[j * PQ + row], lo);
                    atomicAdd(&d_Pb[j * PQ + row], hi);
                }
            }
        }
        beg = rend;
    }
}

// ---------------------------------------------------------------------------
// Zero accumulators
// ---------------------------------------------------------------------------
__global__ void zero_kernel() {
    int i = blockIdx.x * blockDim.x + threadIdx.x;
    if (i < NB * PQ) { d_GN[i] = 0.f; d_Pb[i] = 0.f; }
    if (i < PQ) d_Sel[i] = 0.f;
    if (i < NB) d_cnt[i] = 0;
}

// ---------------------------------------------------------------------------
// Prep: labels int32 -> uint8, histogram counts
// ---------------------------------------------------------------------------
__global__ void prep_kernel(const int* __restrict__ labels) {
    __shared__ int h[NB];
    if (threadIdx.x < NB) h[threadIdx.x] = 0;
    __syncthreads();

    int i = blockIdx.x * blockDim.x + threadIdx.x;
    if (i < PP / 4) {
        int4 l4 = reinterpret_cast<const int4*>(labels)[i];
        uchar4 u;
        u.x = (unsigned char)l4.x; u.y = (unsigned char)l4.y;
        u.z = (unsigned char)l4.z; u.w = (unsigned char)l4.w;
        reinterpret_cast<uchar4*>(d_lab8)[i] = u;
        atomicAdd(&h[l4.x], 1);
        atomicAdd(&h[l4.y], 1);
        atomicAdd(&h[l4.z], 1);
        atomicAdd(&h[l4.w], 1);
    }
    __syncthreads();
    if (threadIdx.x < NB && h[threadIdx.x] != 0)
        atomicAdd(&d_cnt[threadIdx.x], h[threadIdx.x]);
}

// ---------------------------------------------------------------------------
// Finalize: out[q,j] = cost_mask + cost_dice
//   sum_p (f1-f0) = -GN[j,q];  f0 part = 0.75*Sel[q]
// ---------------------------------------------------------------------------
__global__ void finalize_kernel(float* __restrict__ out) {
    int q = blockIdx.x, j = threadIdx.x;   // 128 threads
    __shared__ float red[4];

    float pv = (j < NB) ? d_Pb[j * PQ + q] : 0.f;
    float w = pv;
    #pragma unroll
    for (int o = 16; o; o >>= 1)
        w += __shfl_xor_sync(0xFFFFFFFFu, w, o);
    if ((j & 31) == 0) red[j >> 5] = w;
    __syncthreads();
    float Psum = red[0] + red[1] + red[2] + red[3];

    if (j < NB) {
        float G   = -d_GN[j * PQ + q];
        float cm  = (G + 0.75f * d_Sel[q]) * (1.0f / (float)PP);
        float num = fmaf(2.0f, pv, 1.0f);
        float den = Psum + (float)d_cnt[j] + 1.0f;
        out[q * NB + j] = cm + 1.0f - num / den;
    }
}

// ---------------------------------------------------------------------------
extern "C" void kernel_launch(void* const* d_in, const int* in_sizes, int n_in,
                              void* d_out, int out_size) {
    const float* pm     = (const float*)d_in[0];
    const int*   labels = (const int*)d_in[1];
    (void)in_sizes; (void)n_in; (void)out_size;

    const int smem = NB * NTH * 8;  // 204,800 B
    cudaFuncSetAttribute(cost_kernel, cudaFuncAttributeMaxDynamicSharedMemorySize, smem);

    zero_kernel<<<(NB * PQ + 255) / 256, 256>>>();
    prep_kernel<<<(PP / 4 + 255) / 256, 256>>>(labels);
    cost_kernel<<<NCTA, NTH, smem>>>(pm);
    finalize_kernel<<<PQ, 128>>>((float*)d_out);
}

// round 6
// speedup vs baseline: 1.7582x; 1.7582x over previous
#include <cuda_runtime.h>
#include <stdint.h>

// Problem constants
#define PQ 400
#define PP 200000
#define NB 100
#define NCTA 148
#define NTH 512
#define NWARP_TOT (NCTA * 16)            // 2368 warps chip-wide
#define ROW_F4 (PP / 4)                  // 50,000 float4 per row
#define TOT_F4 ((long long)PQ * ROW_F4)  // 20,000,000

typedef unsigned long long u64;
typedef unsigned int u32;

// Device scratch (no allocations allowed)
__device__ unsigned char d_lab8[PP];
__device__ float d_GN[NB * PQ];   // sum of (sel - 0.25(A+B)) = -(f1-f0) per (label,q)
__device__ float d_Pb[NB * PQ];   // sum of sigmoid per (label,q)
__device__ float d_Sel[PQ];       // sum of sel per q
__device__ int   d_cnt[NB];

// ---------------------------------------------------------------------------
// f32x2 / misc PTX helpers
// ---------------------------------------------------------------------------
#define FMA2(d, a, b, c) asm("fma.rn.f32x2 %0, %1, %2, %3;" : "=l"(d) : "l"(a), "l"(b), "l"(c))
#define MUL2(d, a, b)    asm("mul.rn.f32x2 %0, %1, %2;"     : "=l"(d) : "l"(a), "l"(b))
#define ADD2(d, a, b)    asm("add.rn.f32x2 %0, %1, %2;"     : "=l"(d) : "l"(a), "l"(b))

__device__ __forceinline__ u64 pk2(float lo, float hi) {
    u64 r; asm("mov.b64 %0, {%1, %2};" : "=l"(r) : "f"(lo), "f"(hi)); return r;
}
__device__ __forceinline__ u64 bcast2(float v) {
    u64 r; asm("mov.b64 %0, {%1, %1};" : "=l"(r) : "f"(v)); return r;
}
__device__ __forceinline__ void upk2(u64 v, float& lo, float& hi) {
    asm("mov.b64 {%0, %1}, %2;" : "=f"(lo), "=f"(hi) : "l"(v));
}
__device__ __forceinline__ float ex2f(float x) {
    float r; asm("ex2.approx.ftz.f32 %0, %1;" : "=f"(r) : "f"(x)); return r;
}
__device__ __forceinline__ float rcpf(float x) {
    float r; asm("rcp.approx.ftz.f32 %0, %1;" : "=f"(r) : "f"(x)); return r;
}
__device__ __forceinline__ float slctf(float a, float b, float c) { // c>=0 ? a : b
    float d; asm("slct.f32.f32 %0, %1, %2, %3;" : "=f"(d) : "f"(a), "f"(b), "f"(c)); return d;
}
__device__ __forceinline__ u32 smem_u32(const void* p) {
    u32 a; asm("{ .reg .u64 t; cvta.to.shared.u64 t, %1; cvt.u32.u64 %0, t; }" : "=r"(a) : "l"(p));
    return a;
}
// pack {lo=g, hi=p} as bf16x2
__device__ __forceinline__ u32 cvt_gp(float g, float p) {
    u32 r; asm("cvt.rn.bf16x2.f32 %0, %1, %2;" : "=r"(r) : "f"(p), "f"(g)); return r;
}

// Private-column bin RMW: LDS.32 + packed bf16 add + STS.32 (no atomics, no races)
__device__ __forceinline__ void bin_rmw(u32 addr, u32 add) {
    u32 v;
    asm volatile("ld.shared.b32 %0, [%1];" : "=r"(v) : "r"(addr));
    asm("add.rn.bf16x2 %0, %0, %1;" : "+r"(v) : "r"(add));
    asm volatile("st.shared.b32 [%0], %1;" :: "r"(addr), "r"(v) : "memory");
}

// Loop-invariant packed constants
struct PkConsts {
    u64 nl2e, one, two, neg1;
    u64 c6, c5, c4, c3, c2, c1, c0;
    u64 negq;
};
__device__ __forceinline__ PkConsts make_consts() {
    PkConsts K;
    K.nl2e = bcast2(-1.4426950408889634f);
    K.one  = bcast2(1.0f);
    K.two  = bcast2(2.0f);
    K.neg1 = bcast2(-1.0f);
    // log1p(e) = ln(3/2) + ln(1 + u/3), u = 2e-1, Taylor deg 7
    K.c6 = bcast2(-2.2862368e-4f);
    K.c5 = bcast2( 8.2304527e-4f);
    K.c4 = bcast2(-3.0864198e-3f);
    K.c3 = bcast2( 1.2345679e-2f);
    K.c2 = bcast2(-5.5555556e-2f);
    K.c1 = bcast2( 3.3333333e-1f);
    K.c0 = bcast2( 4.0546511e-1f);
    K.negq = bcast2(-0.25f);
    return K;
}

// ---------------------------------------------------------------------------
// pair2: 2 elements -> two bf16x2 {g,p} bin contributions; selacc += sel (f32x2)
// ---------------------------------------------------------------------------
__device__ __forceinline__ void pair2(u64 X, const PkConsts& K,
                                      u32& bin0, u32& bin1, u64& selacc) {
    u64 AX = X & 0x7FFFFFFF7FFFFFFFull;
    u64 T;  MUL2(T, AX, K.nl2e);
    float t0, t1; upk2(T, t0, t1);
    u64 E = pk2(ex2f(t0), ex2f(t1));
    u64 EP1; ADD2(EP1, E, K.one);
    float q0, q1; upk2(EP1, q0, q1);
    u64 S = pk2(rcpf(q0), rcpf(q1));

    u64 U; FMA2(U, E, K.two, K.neg1);
    u64 L;
    FMA2(L, U, K.c6, K.c5);
    FMA2(L, L, U, K.c4);
    FMA2(L, L, U, K.c3);
    FMA2(L, L, U, K.c2);
    FMA2(L, L, U, K.c1);
    FMA2(L, L, U, K.c0);

    u64 OS;  MUL2(OS, E, S);
    u64 AXL; ADD2(AXL, AX, L);
    u64 OS2; MUL2(OS2, OS, OS);
    u64 Apk; MUL2(Apk, OS2, L);
    u64 S2;  MUL2(S2, S, S);
    u64 Bpk; MUL2(Bpk, S2, AXL);
    u64 ABpk; ADD2(ABpk, Apk, Bpk);

    float a0, a1, b0, b1, x0, x1, os0, os1, s0, s1;
    upk2(Apk, a0, a1); upk2(Bpk, b0, b1);
    upk2(X, x0, x1); upk2(OS, os0, os1); upk2(S, s0, s1);

    float sel0 = slctf(b0, a0, x0);   // x>=0 ? B : A
    float sel1 = slctf(b1, a1, x1);
    float p0   = slctf(s0, os0, x0);  // x>=0 ? s : os
    float p1   = slctf(s1, os1, x1);

    u64 SEL = pk2(sel0, sel1);
    u64 GN;  FMA2(GN, ABpk, K.negq, SEL);   // gneg = sel - 0.25(A+B) = -(f1-f0)
    ADD2(selacc, selacc, SEL);

    float gn0, gn1; upk2(GN, gn0, gn1);
    bin0 = cvt_gp(gn0, p0);
    bin1 = cvt_gp(gn1, p1);
}

__device__ __forceinline__ void proc4(float4 x, u32 lb, u32 sb,
                                      const PkConsts& K, u64& selpk) {
    u32 b0, b1, b2, b3;
    pair2(pk2(x.x, x.y), K, b0, b1, selpk);
    pair2(pk2(x.z, x.w), K, b2, b3, selpk);
    bin_rmw(sb + ( lb        & 0xFFu) * (NTH * 4u), b0);
    bin_rmw(sb + ((lb >>  8) & 0xFFu) * (NTH * 4u), b1);
    bin_rmw(sb + ((lb >> 16) & 0xFFu) * (NTH * 4u), b2);
    bin_rmw(sb + ( lb >> 24         ) * (NTH * 4u), b3);
}

// ---------------------------------------------------------------------------
// Main kernel: flat warp ranges, thread-private bf16x2 bin columns, prefetch x4
// ---------------------------------------------------------------------------
__global__ __launch_bounds__(NTH, 1) void cost_kernel(const float* __restrict__ pm) {
    extern __shared__ u32 bins[];   // [NB][NTH] bf16x2 {g,p}, column = tid (private)
    int tid = threadIdx.x, wid = tid >> 5, lane = tid & 31;

    #pragma unroll 4
    for (int j = 0; j < NB; j++) bins[j * NTH + tid] = 0u;
    // no __syncthreads needed: columns are strictly thread-private

    const PkConsts K = make_consts();
    u32 sb = smem_u32(bins) + (u32)tid * 4u;

    u64 gw = (u64)blockIdx.x * 16 + (u64)wid;
    long long beg = (long long)(gw * (u64)TOT_F4 / NWARP_TOT);
    long long end = (long long)((gw + 1) * (u64)TOT_F4 / NWARP_TOT);

    const u32* lv = reinterpret_cast<const u32*>(d_lab8);  // uchar4 per float4

    while (beg < end) {
        int row = (int)(beg / ROW_F4);
        long long rend = (long long)(row + 1) * ROW_F4;
        if (rend > end) rend = end;
        int c0 = (int)(beg - (long long)row * ROW_F4);
        int cn = (int)(rend - (long long)row * ROW_F4);

        const float4* xr = reinterpret_cast<const float4*>(pm + (size_t)row * PP);

        u64 selpk = 0ull;
        int c = c0 + lane;
        // main loop: 4 float4 in flight per lane (MLP_p1 ~ 8 incl. labels)
        for (; c + 96 < cn; c += 128) {
            float4 x0 = __ldcs(xr + c);
            float4 x1 = __ldcs(xr + c + 32);
            float4 x2 = __ldcs(xr + c + 64);
            float4 x3 = __ldcs(xr + c + 96);
            u32 l0 = lv[c], l1 = lv[c + 32], l2 = lv[c + 64], l3 = lv[c + 96];
            proc4(x0, l0, sb, K, selpk);
            proc4(x1, l1, sb, K, selpk);
            proc4(x2, l2, sb, K, selpk);
            proc4(x3, l3, sb, K, selpk);
        }
        for (; c < cn; c += 32)
            proc4(__ldcs(xr + c), lv[c], sb, K, selpk);

        // ---- segment flush (row uniform across warp) ----
        {
            float slo, shi; upk2(selpk, slo, shi);
            float sv = slo + shi;
            #pragma unroll
            for (int o = 16; o; o >>= 1)
                sv += __shfl_xor_sync(0xFFFFFFFFu, sv, o);
            if (lane == 0) atomicAdd(&d_Sel[row], sv);

            for (int j = 0; j < NB; j++) {
                u32 v = bins[j * NTH + tid];
                bins[j * NTH + tid] = 0u;
                float g = __uint_as_float(v << 16);          // lo bf16 -> f32
                float p = __uint_as_float(v & 0xFFFF0000u);  // hi bf16 -> f32
                #pragma unroll
                for (int o = 16; o; o >>= 1) {
                    g += __shfl_xor_sync(0xFFFFFFFFu, g, o);
                    p += __shfl_xor_sync(0xFFFFFFFFu, p, o);
                }
                if (lane == 0) {
                    atomicAdd(&d_GN[j * PQ + row], g);
                    atomicAdd(&d_Pb[j * PQ + row], p);
                }
            }
        }
        beg = rend;
    }
}

// ---------------------------------------------------------------------------
// Zero accumulators
// ---------------------------------------------------------------------------
__global__ void zero_kernel() {
    int i = blockIdx.x * blockDim.x + threadIdx.x;
    if (i < NB * PQ) { d_GN[i] = 0.f; d_Pb[i] = 0.f; }
    if (i < PQ) d_Sel[i] = 0.f;
    if (i < NB) d_cnt[i] = 0;
}

// ---------------------------------------------------------------------------
// Prep: labels int32 -> uint8, histogram counts
// ---------------------------------------------------------------------------
__global__ void prep_kernel(const int* __restrict__ labels) {
    __shared__ int h[NB];
    if (threadIdx.x < NB) h[threadIdx.x] = 0;
    __syncthreads();

    int i = blockIdx.x * blockDim.x + threadIdx.x;
    if (i < PP / 4) {
        int4 l4 = reinterpret_cast<const int4*>(labels)[i];
        uchar4 u;
        u.x = (unsigned char)l4.x; u.y = (unsigned char)l4.y;
        u.z = (unsigned char)l4.z; u.w = (unsigned char)l4.w;
        reinterpret_cast<uchar4*>(d_lab8)[i] = u;
        atomicAdd(&h[l4.x], 1);
        atomicAdd(&h[l4.y], 1);
        atomicAdd(&h[l4.z], 1);
        atomicAdd(&h[l4.w], 1);
    }
    __syncthreads();
    if (threadIdx.x < NB && h[threadIdx.x] != 0)
        atomicAdd(&d_cnt[threadIdx.x], h[threadIdx.x]);
}

// ---------------------------------------------------------------------------
// Finalize: out[q,j] = cost_mask + cost_dice
// ---------------------------------------------------------------------------
__global__ void finalize_kernel(float* __restrict__ out) {
    int q = blockIdx.x, j = threadIdx.x;   // 128 threads
    __shared__ float red[4];

    float pv = (j < NB) ? d_Pb[j * PQ + q] : 0.f;
    float w = pv;
    #pragma unroll
    for (int o = 16; o; o >>= 1)
        w += __shfl_xor_sync(0xFFFFFFFFu, w, o);
    if ((j & 31) == 0) red[j >> 5] = w;
    __syncthreads();
    float Psum = red[0] + red[1] + red[2] + red[3];

    if (j < NB) {
        float G   = -d_GN[j * PQ + q];
        float cm  = (G + 0.75f * d_Sel[q]) * (1.0f / (float)PP);
        float num = fmaf(2.0f, pv, 1.0f);
        float den = Psum + (float)d_cnt[j] + 1.0f;
        out[q * NB + j] = cm + 1.0f - num / den;
    }
}

// ---------------------------------------------------------------------------
extern "C" void kernel_launch(void* const* d_in, const int* in_sizes, int n_in,
                              void* d_out, int out_size) {
    const float* pm     = (const float*)d_in[0];
    const int*   labels = (const int*)d_in[1];
    (void)in_sizes; (void)n_in; (void)out_size;

    const int smem = NB * NTH * 4;  // 204,800 B
    cudaFuncSetAttribute(cost_kernel, cudaFuncAttributeMaxDynamicSharedMemorySize, smem);

    zero_kernel<<<(NB * PQ + 255) / 256, 256>>>();
    prep_kernel<<<(PP / 4 + 255) / 256, 256>>>(labels);
    cost_kernel<<<NCTA, NTH, smem>>>(pm);
    finalize_kernel<<<PQ, 128>>>((float*)d_out);
}

// round 7
// speedup vs baseline: 1.8707x; 1.0640x over previous
#include <cuda_runtime.h>
#include <stdint.h>

// Problem constants
#define PQ 400
#define PP 200000
#define NB 100
#define NCTA 148
#define NTH 512
#define NWARP_TOT (NCTA * 16)            // 2368 warps chip-wide
#define ROW_F4 (PP / 4)                  // 50,000 float4 per row
#define TOT_F4 ((long long)PQ * ROW_F4)  // 20,000,000

typedef unsigned long long u64;
typedef unsigned int u32;

// Device scratch (no allocations allowed)
__device__ unsigned char d_lab8[PP];
__device__ float d_GN[NB * PQ];   // sum of (sel - 0.25(A+B)) = -(f1-f0) per (label,q)
__device__ float d_Pb[NB * PQ];   // sum of sigmoid per (label,q)
__device__ float d_Sel[PQ];       // sum of sel per q
__device__ int   d_cnt[NB];

// ---------------------------------------------------------------------------
// f32x2 / misc PTX helpers
// ---------------------------------------------------------------------------
#define FMA2(d, a, b, c) asm("fma.rn.f32x2 %0, %1, %2, %3;" : "=l"(d) : "l"(a), "l"(b), "l"(c))
#define MUL2(d, a, b)    asm("mul.rn.f32x2 %0, %1, %2;"     : "=l"(d) : "l"(a), "l"(b))
#define ADD2(d, a, b)    asm("add.rn.f32x2 %0, %1, %2;"     : "=l"(d) : "l"(a), "l"(b))
#define HADD2(d, a)      asm("add.rn.bf16x2 %0, %0, %1;"    : "+r"(d) : "r"(a))

__device__ __forceinline__ u64 pk2(float lo, float hi) {
    u64 r; asm("mov.b64 %0, {%1, %2};" : "=l"(r) : "f"(lo), "f"(hi)); return r;
}
__device__ __forceinline__ u64 bcast2(float v) {
    u64 r; asm("mov.b64 %0, {%1, %1};" : "=l"(r) : "f"(v)); return r;
}
__device__ __forceinline__ void upk2(u64 v, float& lo, float& hi) {
    asm("mov.b64 {%0, %1}, %2;" : "=f"(lo), "=f"(hi) : "l"(v));
}
__device__ __forceinline__ float ex2f(float x) {
    float r; asm("ex2.approx.ftz.f32 %0, %1;" : "=f"(r) : "f"(x)); return r;
}
__device__ __forceinline__ float rcpf(float x) {
    float r; asm("rcp.approx.ftz.f32 %0, %1;" : "=f"(r) : "f"(x)); return r;
}
__device__ __forceinline__ float slctf(float a, float b, float c) { // c>=0 ? a : b
    float d; asm("slct.f32.f32 %0, %1, %2, %3;" : "=f"(d) : "f"(a), "f"(b), "f"(c)); return d;
}
__device__ __forceinline__ u32 smem_u32(const void* p) {
    u32 a; asm("{ .reg .u64 t; cvta.to.shared.u64 t, %1; cvt.u32.u64 %0, t; }" : "=r"(a) : "l"(p));
    return a;
}
// pack {lo=g, hi=p} as bf16x2
__device__ __forceinline__ u32 cvt_gp(float g, float p) {
    u32 r; asm("cvt.rn.bf16x2.f32 %0, %1, %2;" : "=r"(r) : "f"(p), "f"(g)); return r;
}

// Private-column bin RMW: LDS.32 + packed bf16 add + STS.32 (no atomics, no races)
__device__ __forceinline__ void bin_rmw(u32 addr, u32 add) {
    u32 v;
    asm volatile("ld.shared.b32 %0, [%1];" : "=r"(v) : "r"(addr));
    asm("add.rn.bf16x2 %0, %0, %1;" : "+r"(v) : "r"(add));
    asm volatile("st.shared.b32 [%0], %1;" :: "r"(addr), "r"(v) : "memory");
}

// Loop-invariant packed constants
struct PkConsts {
    u64 nl2e, one, two, neg1;
    u64 d4, d3, d2, d1, d0;
    u64 negq;
};
__device__ __forceinline__ PkConsts make_consts() {
    PkConsts K;
    K.nl2e = bcast2(-1.4426950408889634f);
    K.one  = bcast2(1.0f);
    K.two  = bcast2(2.0f);
    K.neg1 = bcast2(-1.0f);
    // deg-4 economized poly for ln(1.5) + ln(1 + u/3), u = 2e-1 in [-1,1]
    K.d4 = bcast2(-3.429356e-3f);
    K.d3 = bcast2( 1.3374487e-2f);
    K.d2 = bcast2(-5.542697e-2f);
    K.d1 = bcast2( 3.3307613e-1f);
    K.d0 = bcast2( 4.0545796e-1f);
    K.negq = bcast2(-0.25f);
    return K;
}

// ---------------------------------------------------------------------------
// pair2: 2 elements -> two bf16x2 {g,p} bin contributions; selacc += sel (f32x2)
// ---------------------------------------------------------------------------
__device__ __forceinline__ void pair2(u64 X, const PkConsts& K,
                                      u32& bin0, u32& bin1, u64& selacc) {
    u64 AX = X & 0x7FFFFFFF7FFFFFFFull;
    u64 T;  MUL2(T, AX, K.nl2e);
    float t0, t1; upk2(T, t0, t1);
    u64 E = pk2(ex2f(t0), ex2f(t1));
    u64 EP1; ADD2(EP1, E, K.one);
    float q0, q1; upk2(EP1, q0, q1);
    u64 S = pk2(rcpf(q0), rcpf(q1));

    u64 U; FMA2(U, E, K.two, K.neg1);
    u64 L;
    FMA2(L, U, K.d4, K.d3);
    FMA2(L, L, U, K.d2);
    FMA2(L, L, U, K.d1);
    FMA2(L, L, U, K.d0);

    u64 OS;  MUL2(OS, E, S);
    u64 AXL; ADD2(AXL, AX, L);
    u64 OS2; MUL2(OS2, OS, OS);
    u64 Apk; MUL2(Apk, OS2, L);
    u64 S2;  MUL2(S2, S, S);
    u64 Bpk; MUL2(Bpk, S2, AXL);
    u64 ABpk; ADD2(ABpk, Apk, Bpk);

    float a0, a1, b0, b1, x0, x1, os0, os1, s0, s1;
    upk2(Apk, a0, a1); upk2(Bpk, b0, b1);
    upk2(X, x0, x1); upk2(OS, os0, os1); upk2(S, s0, s1);

    float sel0 = slctf(b0, a0, x0);   // x>=0 ? B : A
    float sel1 = slctf(b1, a1, x1);
    float p0   = slctf(s0, os0, x0);  // x>=0 ? s : os
    float p1   = slctf(s1, os1, x1);

    u64 SEL = pk2(sel0, sel1);
    u64 GN;  FMA2(GN, ABpk, K.negq, SEL);   // gneg = sel - 0.25(A+B) = -(f1-f0)
    ADD2(selacc, selacc, SEL);

    float gn0, gn1; upk2(GN, gn0, gn1);
    bin0 = cvt_gp(gn0, p0);
    bin1 = cvt_gp(gn1, p1);
}

__device__ __forceinline__ void proc4(float4 x, u32 lb, u32 sb,
                                      const PkConsts& K, u64& selpk) {
    u32 b0, b1, b2, b3;
    pair2(pk2(x.x, x.y), K, b0, b1, selpk);
    pair2(pk2(x.z, x.w), K, b2, b3, selpk);
    bin_rmw(sb + ( lb        & 0xFFu) * (NTH * 4u), b0);
    bin_rmw(sb + ((lb >>  8) & 0xFFu) * (NTH * 4u), b1);
    bin_rmw(sb + ((lb >> 16) & 0xFFu) * (NTH * 4u), b2);
    bin_rmw(sb + ( lb >> 24         ) * (NTH * 4u), b3);
}

// ---------------------------------------------------------------------------
// Main kernel: flat warp ranges, thread-private bf16x2 bin columns,
// 2-deep software pipeline (load batch i+1 before processing batch i)
// ---------------------------------------------------------------------------
__global__ __launch_bounds__(NTH, 1) void cost_kernel(const float* __restrict__ pm) {
    extern __shared__ u32 bins[];   // [NB][NTH] bf16x2 {g,p}, column = tid (private)
    int tid = threadIdx.x, wid = tid >> 5, lane = tid & 31;

    #pragma unroll 4
    for (int j = 0; j < NB; j++) bins[j * NTH + tid] = 0u;
    // no __syncthreads needed: columns are strictly thread-private

    const PkConsts K = make_consts();
    u32 sb = smem_u32(bins) + (u32)tid * 4u;

    u64 gw = (u64)blockIdx.x * 16 + (u64)wid;
    long long beg = (long long)(gw * (u64)TOT_F4 / NWARP_TOT);
    long long end = (long long)((gw + 1) * (u64)TOT_F4 / NWARP_TOT);

    const u32* lv = reinterpret_cast<const u32*>(d_lab8);  // uchar4 per float4

    while (beg < end) {
        int row = (int)(beg / ROW_F4);
        long long rend = (long long)(row + 1) * ROW_F4;
        if (rend > end) rend = end;
        int c0 = (int)(beg - (long long)row * ROW_F4);
        int cn = (int)(rend - (long long)row * ROW_F4);

        const float4* xr = reinterpret_cast<const float4*>(pm + (size_t)row * PP);

        u64 selpk = 0ull;
        int cL = c0 + lane;
        int nfull = (cn - c0) >> 7;      // number of full 128-f4 batches (warp-uniform)

        float4 xb[2][4]; u32 lbv[2][4];

#define LOADB(b, cc) do {                                            \
            xb[b][0] = __ldcs(xr + (cc));                            \
            xb[b][1] = __ldcs(xr + (cc) + 32);                       \
            xb[b][2] = __ldcs(xr + (cc) + 64);                       \
            xb[b][3] = __ldcs(xr + (cc) + 96);                       \
            lbv[b][0] = lv[(cc)];        lbv[b][1] = lv[(cc) + 32];  \
            lbv[b][2] = lv[(cc) + 64];   lbv[b][3] = lv[(cc) + 96];  \
        } while (0)
#define PROCB(b) do {                                                \
            proc4(xb[b][0], lbv[b][0], sb, K, selpk);                \
            proc4(xb[b][1], lbv[b][1], sb, K, selpk);                \
            proc4(xb[b][2], lbv[b][2], sb, K, selpk);                \
            proc4(xb[b][3], lbv[b][3], sb, K, selpk);                \
        } while (0)

        if (nfull > 0) {
            LOADB(0, cL);
            #pragma unroll 2
            for (int i = 1; i < nfull; i++) {
                int b = i & 1;
                LOADB(b, cL + (i << 7));
                PROCB(b ^ 1);
            }
            PROCB((nfull - 1) & 1);
            cL += nfull << 7;
        }
        for (; cL < cn; cL += 32)
            proc4(__ldcs(xr + cL), lv[cL], sb, K, selpk);

        // ---- segment flush (row uniform across warp) ----
        {
            float slo, shi; upk2(selpk, slo, shi);
            float sv = slo + shi;
            #pragma unroll
            for (int o = 16; o; o >>= 1)
                sv += __shfl_xor_sync(0xFFFFFFFFu, sv, o);
            if (lane == 0) atomicAdd(&d_Sel[row], sv);

            for (int j = 0; j < NB; j++) {
                u32 v = bins[j * NTH + tid];
                bins[j * NTH + tid] = 0u;
                // 3 packed bf16 reduce levels (16, 8, 4)
                u32 t;
                t = __shfl_xor_sync(0xFFFFFFFFu, v, 16); HADD2(v, t);
                t = __shfl_xor_sync(0xFFFFFFFFu, v, 8);  HADD2(v, t);
                t = __shfl_xor_sync(0xFFFFFFFFu, v, 4);  HADD2(v, t);
                // unpack, finish in f32 (levels 2, 1)
                float g = __uint_as_float(v << 16);
                float p = __uint_as_float(v & 0xFFFF0000u);
                #pragma unroll
                for (int o = 2; o; o >>= 1) {
                    g += __shfl_xor_sync(0xFFFFFFFFu, g, o);
                    p += __shfl_xor_sync(0xFFFFFFFFu, p, o);
                }
                if (lane == 0)  atomicAdd(&d_GN[j * PQ + row], g);
                if (lane == 16) atomicAdd(&d_Pb[j * PQ + row], p);
            }
        }
        beg = rend;
    }
#undef LOADB
#undef PROCB
}

// ---------------------------------------------------------------------------
// Zero d_cnt (must precede prep's atomics)
// ---------------------------------------------------------------------------
__global__ void zero_kernel() {
    if (threadIdx.x < NB) d_cnt[threadIdx.x] = 0;
}

// ---------------------------------------------------------------------------
// Prep: labels int32 -> uint8, histogram counts, zero accumulators
// ---------------------------------------------------------------------------
__global__ void prep_kernel(const int* __restrict__ labels) {
    __shared__ int h[NB];
    if (threadIdx.x < NB) h[threadIdx.x] = 0;
    __syncthreads();

    int i = blockIdx.x * blockDim.x + threadIdx.x;
    if (i < NB * PQ) { d_GN[i] = 0.f; d_Pb[i] = 0.f; }
    if (i < PQ) d_Sel[i] = 0.f;

    if (i < PP / 4) {
        int4 l4 = reinterpret_cast<const int4*>(labels)[i];
        uchar4 u;
        u.x = (unsigned char)l4.x; u.y = (unsigned char)l4.y;
        u.z = (unsigned char)l4.z; u.w = (unsigned char)l4.w;
        reinterpret_cast<uchar4*>(d_lab8)[i] = u;
        atomicAdd(&h[l4.x], 1);
        atomicAdd(&h[l4.y], 1);
        atomicAdd(&h[l4.z], 1);
        atomicAdd(&h[l4.w], 1);
    }
    __syncthreads();
    if (threadIdx.x < NB && h[threadIdx.x] != 0)
        atomicAdd(&d_cnt[threadIdx.x], h[threadIdx.x]);
}

// ---------------------------------------------------------------------------
// Finalize: out[q,j] = cost_mask + cost_dice
// ---------------------------------------------------------------------------
__global__ void finalize_kernel(float* __restrict__ out) {
    int q = blockIdx.x, j = threadIdx.x;   // 128 threads
    __shared__ float red[4];

    float pv = (j < NB) ? d_Pb[j * PQ + q] : 0.f;
    float w = pv;
    #pragma unroll
    for (int o = 16; o; o >>= 1)
        w += __shfl_xor_sync(0xFFFFFFFFu, w, o);
    if ((j & 31) == 0) red[j >> 5] = w;
    __syncthreads();
    float Psum = red[0] + red[1] + red[2] + red[3];

    if (j < NB) {
        float G   = -d_GN[j * PQ + q];
        float cm  = (G + 0.75f * d_Sel[q]) * (1.0f / (float)PP);
        float num = fmaf(2.0f, pv, 1.0f);
        float den = Psum + (float)d_cnt[j] + 1.0f;
        out[q * NB + j] = cm + 1.0f - num / den;
    }
}

// ---------------------------------------------------------------------------
extern "C" void kernel_launch(void* const* d_in, const int* in_sizes, int n_in,
                              void* d_out, int out_size) {
    const float* pm     = (const float*)d_in[0];
    const int*   labels = (const int*)d_in[1];
    (void)in_sizes; (void)n_in; (void)out_size;

    const int smem = NB * NTH * 4;  // 204,800 B
    cudaFuncSetAttribute(cost_kernel, cudaFuncAttributeMaxDynamicSharedMemorySize, smem);

    zero_kernel<<<1, 128>>>();
    prep_kernel<<<(PP / 4 + 255) / 256, 256>>>(labels);
    cost_kernel<<<NCTA, NTH, smem>>>(pm);
    finalize_kernel<<<PQ, 128>>>((float*)d_out);
}